// round 4
// baseline (speedup 1.0000x reference)
#include <cuda_runtime.h>
#include <mma.h>
#include <math.h>

using namespace nvcuda;

// Problem constants
#define TT    256
#define BSZ   64
#define DIN   1024
#define HIDN  1024
#define NL    2
#define H4    (4 * HIDN)
#define MTOT  (TT * BSZ)          // 16384
#define BH    (BSZ * HIDN)        // 65536

// ---------------- device scratch (no allocations allowed) ----------------
__device__ float g_Xp[(size_t)MTOT * H4];   // precomputed x@Wx^T + b for current layer (256 MB)
__device__ float g_H0[(size_t)MTOT * HIDN]; // layer-0 hidden outputs for all t (64 MB)
__device__ float g_c[NL][BH];               // cell states
__device__ float g_zero[BH];                // all-zero h for t=0

// ---------------- init: zero cell states ----------------
__global__ void init_kernel() {
    int i = blockIdx.x * blockDim.x + threadIdx.x;
    if (i < BH) {
        g_c[0][i] = 0.f;
        g_c[1][i] = 0.f;
        g_zero[i] = 0.f;
    }
}

// ---------------- precompute GEMM: C = A[M,K] @ W[N,K]^T + bias[N] -> g_Xp ----------------
// tf32 wmma, 64x64 block tile, K-tile 32, 256 threads (8 warps: 4 m-tiles x 2 n-tiles)
__global__ void gemm_xp_kernel(const float* __restrict__ A,
                               const float* __restrict__ W,
                               const float* __restrict__ bias,
                               int M, int N, int K) {
    __shared__ float As[64][36];
    __shared__ float Ws[64][36];
    __shared__ float Cs[64][68];

    const int tid  = threadIdx.x;
    const int warp = tid >> 5;
    const int wm   = warp & 3;    // 0..3 -> 16-row slice
    const int wn   = warp >> 2;   // 0..1 -> 32-col slice
    const int row0A = blockIdx.y * 64;
    const int row0W = blockIdx.x * 64;

    wmma::fragment<wmma::accumulator, 16, 16, 8, float> acc[2];
    wmma::fill_fragment(acc[0], 0.f);
    wmma::fill_fragment(acc[1], 0.f);

    for (int k0 = 0; k0 < K; k0 += 32) {
#pragma unroll
        for (int r = 0; r < 2; r++) {
            int row = r * 32 + (tid >> 3);
            int c4  = (tid & 7) * 4;
            *(float4*)&As[row][c4] =
                *(const float4*)(A + (size_t)(row0A + row) * K + k0 + c4);
            *(float4*)&Ws[row][c4] =
                *(const float4*)(W + (size_t)(row0W + row) * K + k0 + c4);
        }
        __syncthreads();
#pragma unroll
        for (int kk = 0; kk < 32; kk += 8) {
            wmma::fragment<wmma::matrix_a, 16, 16, 8, wmma::precision::tf32, wmma::row_major> af;
            wmma::load_matrix_sync(af, &As[wm * 16][kk], 36);
#pragma unroll
            for (int i = 0; i < af.num_elements; i++) af.x[i] = wmma::__float_to_tf32(af.x[i]);
#pragma unroll
            for (int j = 0; j < 2; j++) {
                wmma::fragment<wmma::matrix_b, 16, 16, 8, wmma::precision::tf32, wmma::col_major> bf;
                wmma::load_matrix_sync(bf, &Ws[wn * 32 + j * 16][kk], 36);
#pragma unroll
                for (int i = 0; i < bf.num_elements; i++) bf.x[i] = wmma::__float_to_tf32(bf.x[i]);
                wmma::mma_sync(acc[j], af, bf, acc[j]);
            }
        }
        __syncthreads();
    }

    wmma::store_matrix_sync(&Cs[wm * 16][wn * 32],      acc[0], 68, wmma::mem_row_major);
    wmma::store_matrix_sync(&Cs[wm * 16][wn * 32 + 16], acc[1], 68, wmma::mem_row_major);
    __syncthreads();

    for (int idx = tid; idx < 64 * 64; idx += 256) {
        int r = idx >> 6, c = idx & 63;
        g_Xp[(size_t)(row0A + r) * N + row0W + c] = Cs[r][c] + bias[row0W + c];
    }
}

// ---------------- fused recurrent step ----------------
// One kernel per (layer, t). Grid = 64 CTAs, each owns 16 hidden units across
// all 4 gates (64 Wh rows) and all 64 batch rows. GEMM partial h@Wh^T (tf32 wmma)
// then LSTM cell epilogue in the same kernel.
__global__ void lstm_step_kernel(const float* __restrict__ Hprev, // [BSZ, HIDN]
                                 const float* __restrict__ Wh,    // [H4, HIDN]
                                 const float* __restrict__ Xp,    // [BSZ, H4] (row t)
                                 float* __restrict__ Hout,        // [BSZ, HIDN]
                                 int layer) {
    __shared__ float As[64][36];
    __shared__ float Ws[64][36];
    __shared__ float Gs[64][68];

    const int tid  = threadIdx.x;
    const int warp = tid >> 5;
    const int gate = warp >> 1;   // 0..3
    const int wm   = warp & 1;    // 0..1 -> 32 batch rows
    const int j0   = blockIdx.x * 16;

    wmma::fragment<wmma::accumulator, 16, 16, 8, float> acc[2];
    wmma::fill_fragment(acc[0], 0.f);
    wmma::fill_fragment(acc[1], 0.f);

    for (int k0 = 0; k0 < HIDN; k0 += 32) {
#pragma unroll
        for (int r = 0; r < 2; r++) {
            int row = r * 32 + (tid >> 3);
            int c4  = (tid & 7) * 4;
            *(float4*)&As[row][c4] =
                *(const float4*)(Hprev + (size_t)row * HIDN + k0 + c4);
            int g_ = row >> 4;            // gate of this smem row
            int u  = row & 15;            // unit within CTA slice
            int wr = g_ * HIDN + j0 + u;  // Wh global row
            *(float4*)&Ws[row][c4] =
                *(const float4*)(Wh + (size_t)wr * HIDN + k0 + c4);
        }
        __syncthreads();
#pragma unroll
        for (int kk = 0; kk < 32; kk += 8) {
            wmma::fragment<wmma::matrix_b, 16, 16, 8, wmma::precision::tf32, wmma::col_major> bf;
            wmma::load_matrix_sync(bf, &Ws[gate * 16][kk], 36);
#pragma unroll
            for (int i = 0; i < bf.num_elements; i++) bf.x[i] = wmma::__float_to_tf32(bf.x[i]);
#pragma unroll
            for (int f = 0; f < 2; f++) {
                wmma::fragment<wmma::matrix_a, 16, 16, 8, wmma::precision::tf32, wmma::row_major> af;
                wmma::load_matrix_sync(af, &As[wm * 32 + f * 16][kk], 36);
#pragma unroll
                for (int i = 0; i < af.num_elements; i++) af.x[i] = wmma::__float_to_tf32(af.x[i]);
                wmma::mma_sync(acc[f], af, bf, acc[f]);
            }
        }
        __syncthreads();
    }

    wmma::store_matrix_sync(&Gs[wm * 32][gate * 16],      acc[0], 68, wmma::mem_row_major);
    wmma::store_matrix_sync(&Gs[wm * 32 + 16][gate * 16], acc[1], 68, wmma::mem_row_major);
    __syncthreads();

    // LSTM cell epilogue: 64 batch x 16 units = 1024 elements, 4 per thread
    for (int idx = tid; idx < 64 * 16; idx += 256) {
        int b_ = idx >> 4;
        int u  = idx & 15;
        int j  = j0 + u;
        const float* xb = Xp + (size_t)b_ * H4;
        float gi = Gs[b_][u]           + xb[j];
        float gf = Gs[b_][16 + u]      + xb[HIDN + j];
        float go = Gs[b_][32 + u]      + xb[2 * HIDN + j];
        float gc = Gs[b_][48 + u]      + xb[3 * HIDN + j];
        float si = 1.f / (1.f + expf(-gi));
        float sf = 1.f / (1.f + expf(-gf));
        float so = 1.f / (1.f + expf(-go));
        float cold = g_c[layer][b_ * HIDN + j];
        float cn = sf * cold + si * tanhf(gc);
        float h  = so * tanhf(cn);
        g_c[layer][b_ * HIDN + j] = cn;
        Hout[(size_t)b_ * HIDN + j] = h;
    }
}

// ---------------- finalize: Hf / Cf ----------------
__global__ void finalize_kernel(const float* __restrict__ h0_last,
                                const float* __restrict__ h1_last,
                                float* __restrict__ Hf,
                                float* __restrict__ Cf) {
    int i = blockIdx.x * blockDim.x + threadIdx.x;
    if (i < BH) {
        Hf[i]      = h0_last[i];
        Hf[BH + i] = h1_last[i];
        Cf[i]      = g_c[0][i];
        Cf[BH + i] = g_c[1][i];
    }
}

// ---------------- launch ----------------
extern "C" void kernel_launch(void* const* d_in, const int* in_sizes, int n_in,
                              void* d_out, int out_size) {
    const float* X    = (const float*)d_in[0]; // [T, B, D]
    const float* Wx   = (const float*)d_in[1]; // [L, 4H, D]
    const float* Wh   = (const float*)d_in[2]; // [L, 4H, H]
    const float* bias = (const float*)d_in[3]; // [L, 4H]

    float* out     = (float*)d_out;
    float* outputs = out;                       // [T, B, H]
    float* Hf      = out + (size_t)TT * BH / 1; // after outputs
    Hf = out + (size_t)TT * BSZ * HIDN;
    float* Cf      = Hf + (size_t)NL * BH;

    float *Xp_p = nullptr, *H0_p = nullptr, *zero_p = nullptr;
    cudaGetSymbolAddress((void**)&Xp_p, g_Xp);
    cudaGetSymbolAddress((void**)&H0_p, g_H0);
    cudaGetSymbolAddress((void**)&zero_p, g_zero);

    init_kernel<<<(BH + 255) / 256, 256>>>();

    dim3 gg(H4 / 64, MTOT / 64);

    // Layer 0: precompute X @ Wx0^T + b0
    gemm_xp_kernel<<<gg, 256>>>(X, Wx, bias, MTOT, H4, DIN);
    // Layer 0 recurrence
    for (int t = 0; t < TT; t++) {
        const float* hp = t ? (H0_p + (size_t)(t - 1) * BH / 1) : zero_p;
        hp = t ? (H0_p + (size_t)(t - 1) * BSZ * HIDN) : zero_p;
        lstm_step_kernel<<<64, 256>>>(hp, Wh,
                                      Xp_p + (size_t)t * BSZ * H4,
                                      H0_p + (size_t)t * BSZ * HIDN, 0);
    }

    // Layer 1: precompute H0 @ Wx1^T + b1
    gemm_xp_kernel<<<gg, 256>>>(H0_p, Wx + (size_t)H4 * DIN, bias + H4, MTOT, H4, HIDN);
    // Layer 1 recurrence (writes directly to outputs region of d_out)
    for (int t = 0; t < TT; t++) {
        const float* hp = t ? (outputs + (size_t)(t - 1) * BSZ * HIDN) : zero_p;
        lstm_step_kernel<<<64, 256>>>(hp, Wh + (size_t)H4 * HIDN,
                                      Xp_p + (size_t)t * BSZ * H4,
                                      outputs + (size_t)t * BSZ * HIDN, 1);
    }

    finalize_kernel<<<(BH + 255) / 256, 256>>>(
        H0_p + (size_t)(TT - 1) * BSZ * HIDN,
        outputs + (size_t)(TT - 1) * BSZ * HIDN,
        Hf, Cf);
}

// round 5
// speedup vs baseline: 1.6146x; 1.6146x over previous
#include <cuda_runtime.h>
#include <mma.h>
#include <math.h>

using namespace nvcuda;

// Problem constants
#define TT    256
#define BSZ   64
#define DIN   1024
#define HIDN  1024
#define NL    2
#define H4    (4 * HIDN)
#define MTOT  (TT * BSZ)          // 16384
#define BH    (BSZ * HIDN)        // 65536

#define NCTA  128                 // persistent CTAs (<= 148 SMs, all co-resident)
#define UPC   8                   // hidden units per CTA (128 * 8 = 1024)

// ---------------- device scratch (no allocations allowed) ----------------
__device__ float g_Xp[(size_t)MTOT * H4];   // precomputed x@Wx^T + b for current layer
__device__ float g_H0[(size_t)MTOT * HIDN]; // layer-0 hidden outputs for all t
__device__ float g_c[NL][BH];               // final cell states
__device__ unsigned g_bar;                  // grid barrier counter

// ---------------- barrier reset ----------------
__global__ void reset_bar_kernel() {
    if (threadIdx.x == 0) g_bar = 0u;
}

// ---------------- precompute GEMM: C = A[M,K] @ W[N,K]^T + bias[N] -> g_Xp ----------------
__global__ void gemm_xp_kernel(const float* __restrict__ A,
                               const float* __restrict__ W,
                               const float* __restrict__ bias,
                               int M, int N, int K) {
    __shared__ float As[64][36];
    __shared__ float Ws[64][36];
    __shared__ float Cs[64][68];

    const int tid  = threadIdx.x;
    const int warp = tid >> 5;
    const int wm   = warp & 3;
    const int wn   = warp >> 2;
    const int row0A = blockIdx.y * 64;
    const int row0W = blockIdx.x * 64;

    wmma::fragment<wmma::accumulator, 16, 16, 8, float> acc[2];
    wmma::fill_fragment(acc[0], 0.f);
    wmma::fill_fragment(acc[1], 0.f);

    for (int k0 = 0; k0 < K; k0 += 32) {
#pragma unroll
        for (int r = 0; r < 2; r++) {
            int row = r * 32 + (tid >> 3);
            int c4  = (tid & 7) * 4;
            *(float4*)&As[row][c4] =
                *(const float4*)(A + (size_t)(row0A + row) * K + k0 + c4);
            *(float4*)&Ws[row][c4] =
                *(const float4*)(W + (size_t)(row0W + row) * K + k0 + c4);
        }
        __syncthreads();
#pragma unroll
        for (int kk = 0; kk < 32; kk += 8) {
            wmma::fragment<wmma::matrix_a, 16, 16, 8, wmma::precision::tf32, wmma::row_major> af;
            wmma::load_matrix_sync(af, &As[wm * 16][kk], 36);
#pragma unroll
            for (int i = 0; i < af.num_elements; i++) af.x[i] = wmma::__float_to_tf32(af.x[i]);
#pragma unroll
            for (int j = 0; j < 2; j++) {
                wmma::fragment<wmma::matrix_b, 16, 16, 8, wmma::precision::tf32, wmma::col_major> bf;
                wmma::load_matrix_sync(bf, &Ws[wn * 32 + j * 16][kk], 36);
#pragma unroll
                for (int i = 0; i < bf.num_elements; i++) bf.x[i] = wmma::__float_to_tf32(bf.x[i]);
                wmma::mma_sync(acc[j], af, bf, acc[j]);
            }
        }
        __syncthreads();
    }

    wmma::store_matrix_sync(&Cs[wm * 16][wn * 32],      acc[0], 68, wmma::mem_row_major);
    wmma::store_matrix_sync(&Cs[wm * 16][wn * 32 + 16], acc[1], 68, wmma::mem_row_major);
    __syncthreads();

    for (int idx = tid; idx < 64 * 64; idx += 256) {
        int r = idx >> 6, c = idx & 63;
        g_Xp[(size_t)(row0A + r) * N + row0W + c] = Cs[r][c] + bias[row0W + c];
    }
}

// ---------------- persistent recurrence: one kernel per layer ----------------
// 128 CTAs x 256 threads. Each CTA owns UPC=8 hidden units (32 Wh rows across
// the 4 gates), preloads its Wh slice into SMEM ONCE, keeps cell state in SMEM,
// and loops over all 256 timesteps with a software grid barrier between steps.
#define SM_WS   0
#define SM_HS   (32 * 1032)
#define SM_GS   (SM_HS + 64 * 68)
#define SM_CS   (SM_GS + 64 * 36)
#define SM_FLOATS (SM_CS + 512)

__global__ void __launch_bounds__(256, 1)
lstm_seq_kernel(const float* __restrict__ Wh,   // [H4, HIDN] layer base
                const float* __restrict__ Xp,   // [TT, BSZ, H4]
                float* Htraj,                   // [TT, BSZ, HIDN] h trajectory (rw)
                float* __restrict__ gC) {       // [BSZ, HIDN] final cell state out
    extern __shared__ float sm[];
    float* Ws = sm + SM_WS;
    float* Hs = sm + SM_HS;
    float* Gs = sm + SM_GS;
    float* cs = sm + SM_CS;

    const int tid  = threadIdx.x;
    const int warp = tid >> 5;
    const int wm   = warp & 3;    // 16-batch slice
    const int wn   = warp >> 2;   // 16-column (N) slice of the CTA's 32
    const int j0   = blockIdx.x * UPC;

    // ---- preload Wh slice: row n (0..31) = gate (n>>3), unit (n&7) ----
    for (int i4 = tid; i4 < 32 * 256; i4 += 256) {
        int n  = i4 >> 8;
        int c4 = (i4 & 255) * 4;
        int row = (n >> 3) * HIDN + j0 + (n & 7);
        *(float4*)&Ws[n * 1032 + c4] = *(const float4*)(Wh + (size_t)row * HIDN + c4);
    }
    for (int i = tid; i < 512; i += 256) cs[i] = 0.f;
    __syncthreads();

    const int r0 = tid >> 4;          // staging row base
    const int c4 = (tid & 15) * 4;    // staging col (float4)

    for (int t = 0; t < TT; t++) {
        wmma::fragment<wmma::accumulator, 16, 16, 8, float> acc;
        wmma::fill_fragment(acc, 0.f);

        if (t > 0) {
            const float* Hprev = Htraj + (size_t)(t - 1) * BH;
            float4 pf[4];
#pragma unroll
            for (int r = 0; r < 4; r++)
                pf[r] = *(const float4*)(Hprev + (size_t)(r0 + r * 16) * HIDN + c4);

            for (int it = 0; it < 16; it++) {
#pragma unroll
                for (int r = 0; r < 4; r++)
                    *(float4*)&Hs[(r0 + r * 16) * 68 + c4] = pf[r];
                __syncthreads();
                if (it < 15) {
                    int k0n = (it + 1) * 64;
#pragma unroll
                    for (int r = 0; r < 4; r++)
                        pf[r] = *(const float4*)(Hprev + (size_t)(r0 + r * 16) * HIDN + k0n + c4);
                }
#pragma unroll
                for (int kk = 0; kk < 64; kk += 8) {
                    wmma::fragment<wmma::matrix_a, 16, 16, 8, wmma::precision::tf32, wmma::row_major> af;
                    wmma::load_matrix_sync(af, &Hs[(wm * 16) * 68 + kk], 68);
#pragma unroll
                    for (int i = 0; i < af.num_elements; i++) af.x[i] = wmma::__float_to_tf32(af.x[i]);
                    wmma::fragment<wmma::matrix_b, 16, 16, 8, wmma::precision::tf32, wmma::col_major> bf;
                    wmma::load_matrix_sync(bf, &Ws[(wn * 16) * 1032 + it * 64 + kk], 1032);
#pragma unroll
                    for (int i = 0; i < bf.num_elements; i++) bf.x[i] = wmma::__float_to_tf32(bf.x[i]);
                    wmma::mma_sync(acc, af, bf, acc);
                }
                __syncthreads();
            }
        }

        wmma::store_matrix_sync(&Gs[(wm * 16) * 36 + wn * 16], acc, 36, wmma::mem_row_major);
        __syncthreads();

        // ---- LSTM cell epilogue: 64 batch x 8 units ----
        const float* xp_t   = Xp + (size_t)t * BSZ * H4;
        float*       hout_t = Htraj + (size_t)t * BH;
        for (int idx = tid; idx < 512; idx += 256) {
            int b = idx >> 3;
            int u = idx & 7;
            const float* xb = xp_t + (size_t)b * H4 + j0 + u;
            float gi = Gs[b * 36 + u]      + xb[0];
            float gf = Gs[b * 36 + 8 + u]  + xb[HIDN];
            float go = Gs[b * 36 + 16 + u] + xb[2 * HIDN];
            float gc = Gs[b * 36 + 24 + u] + xb[3 * HIDN];
            float si = 1.f / (1.f + expf(-gi));
            float sf = 1.f / (1.f + expf(-gf));
            float so = 1.f / (1.f + expf(-go));
            float cn = sf * cs[idx] + si * tanhf(gc);
            cs[idx] = cn;
            hout_t[(size_t)b * HIDN + j0 + u] = so * tanhf(cn);
        }

        // ---- grid barrier: release h(t) to all CTAs ----
        __threadfence();
        __syncthreads();
        if (tid == 0) {
            atomicAdd(&g_bar, 1u);
            unsigned target = (unsigned)(t + 1) * NCTA;
            while (*((volatile unsigned*)&g_bar) < target) __nanosleep(32);
        }
        __syncthreads();
        __threadfence();
    }

    // ---- write final cell state ----
    for (int idx = tid; idx < 512; idx += 256) {
        int b = idx >> 3;
        int u = idx & 7;
        gC[(size_t)b * HIDN + j0 + u] = cs[idx];
    }
}

// ---------------- finalize: Hf / Cf ----------------
__global__ void finalize_kernel(const float* __restrict__ h0_last,
                                const float* __restrict__ h1_last,
                                float* __restrict__ Hf,
                                float* __restrict__ Cf) {
    int i = blockIdx.x * blockDim.x + threadIdx.x;
    if (i < BH) {
        Hf[i]      = h0_last[i];
        Hf[BH + i] = h1_last[i];
        Cf[i]      = g_c[0][i];
        Cf[BH + i] = g_c[1][i];
    }
}

// ---------------- launch ----------------
extern "C" void kernel_launch(void* const* d_in, const int* in_sizes, int n_in,
                              void* d_out, int out_size) {
    const float* X    = (const float*)d_in[0]; // [T, B, D]
    const float* Wx   = (const float*)d_in[1]; // [L, 4H, D]
    const float* Wh   = (const float*)d_in[2]; // [L, 4H, H]
    const float* bias = (const float*)d_in[3]; // [L, 4H]

    float* out     = (float*)d_out;
    float* outputs = out;                              // [T, B, H]
    float* Hf      = out + (size_t)TT * BSZ * HIDN;
    float* Cf      = Hf + (size_t)NL * BH;

    float *Xp_p = nullptr, *H0_p = nullptr, *gc_p = nullptr;
    cudaGetSymbolAddress((void**)&Xp_p, g_Xp);
    cudaGetSymbolAddress((void**)&H0_p, g_H0);
    cudaGetSymbolAddress((void**)&gc_p, g_c);

    static bool attr_set = false;
    if (!attr_set) {
        cudaFuncSetAttribute(lstm_seq_kernel,
                             cudaFuncAttributeMaxDynamicSharedMemorySize,
                             SM_FLOATS * sizeof(float));
        attr_set = true;
    }

    dim3 gg(H4 / 64, MTOT / 64);

    // Layer 0: precompute X @ Wx0^T + b0, then persistent recurrence
    gemm_xp_kernel<<<gg, 256>>>(X, Wx, bias, MTOT, H4, DIN);
    reset_bar_kernel<<<1, 32>>>();
    lstm_seq_kernel<<<NCTA, 256, SM_FLOATS * sizeof(float)>>>(
        Wh, Xp_p, H0_p, gc_p);

    // Layer 1: precompute H0 @ Wx1^T + b1, then persistent recurrence
    gemm_xp_kernel<<<gg, 256>>>(H0_p, Wx + (size_t)H4 * DIN, bias + H4, MTOT, H4, HIDN);
    reset_bar_kernel<<<1, 32>>>();
    lstm_seq_kernel<<<NCTA, 256, SM_FLOATS * sizeof(float)>>>(
        Wh + (size_t)H4 * HIDN, Xp_p, outputs, gc_p + BH);

    finalize_kernel<<<(BH + 255) / 256, 256>>>(
        H0_p + (size_t)(TT - 1) * BH,
        outputs + (size_t)(TT - 1) * BH,
        Hf, Cf);
}

// round 6
// speedup vs baseline: 1.9300x; 1.1953x over previous
#include <cuda_runtime.h>
#include <mma.h>
#include <math.h>

using namespace nvcuda;

// Problem constants
#define TT    256
#define BSZ   64
#define DIN   1024
#define HIDN  1024
#define NL    2
#define H4    (4 * HIDN)
#define MTOT  (TT * BSZ)          // 16384
#define BH    (BSZ * HIDN)        // 65536

#define NCTA  128                 // persistent CTAs, 1 per SM
#define UPC   8                   // hidden units per CTA (128 * 8 = 1024); 32 gate-cols per CTA
#define NTHR  512                 // 16 warps: 2 K-halves x 4 batch-tiles x 2 col-tiles

// ---------------- device scratch (no allocations allowed) ----------------
__device__ float g_Xp[(size_t)MTOT * H4];   // precomputed x@Wx^T + b for current layer
__device__ float g_H0[(size_t)MTOT * HIDN]; // layer-0 hidden outputs for all t
__device__ float g_c[NL][BH];               // final cell states
__device__ unsigned g_bar;                  // grid barrier counter

__global__ void reset_bar_kernel() {
    if (threadIdx.x == 0) g_bar = 0u;
}

// ---------------- precompute GEMM: C = A[M,K] @ W[N,K]^T + bias[N] -> g_Xp ----------------
__global__ void gemm_xp_kernel(const float* __restrict__ A,
                               const float* __restrict__ W,
                               const float* __restrict__ bias,
                               int M, int N, int K) {
    __shared__ float As[64][36];
    __shared__ float Ws[64][36];
    __shared__ float Cs[64][68];

    const int tid  = threadIdx.x;
    const int warp = tid >> 5;
    const int wm   = warp & 3;
    const int wn   = warp >> 2;
    const int row0A = blockIdx.y * 64;
    const int row0W = blockIdx.x * 64;

    wmma::fragment<wmma::accumulator, 16, 16, 8, float> acc[2];
    wmma::fill_fragment(acc[0], 0.f);
    wmma::fill_fragment(acc[1], 0.f);

    for (int k0 = 0; k0 < K; k0 += 32) {
#pragma unroll
        for (int r = 0; r < 2; r++) {
            int row = r * 32 + (tid >> 3);
            int c4  = (tid & 7) * 4;
            *(float4*)&As[row][c4] =
                *(const float4*)(A + (size_t)(row0A + row) * K + k0 + c4);
            *(float4*)&Ws[row][c4] =
                *(const float4*)(W + (size_t)(row0W + row) * K + k0 + c4);
        }
        __syncthreads();
#pragma unroll
        for (int kk = 0; kk < 32; kk += 8) {
            wmma::fragment<wmma::matrix_a, 16, 16, 8, wmma::precision::tf32, wmma::row_major> af;
            wmma::load_matrix_sync(af, &As[wm * 16][kk], 36);
#pragma unroll
            for (int i = 0; i < af.num_elements; i++) af.x[i] = wmma::__float_to_tf32(af.x[i]);
#pragma unroll
            for (int j = 0; j < 2; j++) {
                wmma::fragment<wmma::matrix_b, 16, 16, 8, wmma::precision::tf32, wmma::col_major> bf;
                wmma::load_matrix_sync(bf, &Ws[wn * 32 + j * 16][kk], 36);
#pragma unroll
                for (int i = 0; i < bf.num_elements; i++) bf.x[i] = wmma::__float_to_tf32(bf.x[i]);
                wmma::mma_sync(acc[j], af, bf, acc[j]);
            }
        }
        __syncthreads();
    }

    wmma::store_matrix_sync(&Cs[wm * 16][wn * 32],      acc[0], 68, wmma::mem_row_major);
    wmma::store_matrix_sync(&Cs[wm * 16][wn * 32 + 16], acc[1], 68, wmma::mem_row_major);
    __syncthreads();

    for (int idx = tid; idx < 64 * 64; idx += 256) {
        int r = idx >> 6, c = idx & 63;
        g_Xp[(size_t)(row0A + r) * N + row0W + c] = Cs[r][c] + bias[row0W + c];
    }
}

// ---------------- persistent recurrence ----------------
// 128 CTAs x 512 threads. CTA owns 8 hidden units (32 gate-cols). Wh slice in
// SMEM (loaded once). 16 warps: wk = K-half, wm = 16-batch tile, wn = 16-col
// tile. Per step: 8 staged K-chunks of 128, 2 accumulators per warp, K-split
// partials summed in epilogue. Grid barrier between steps.
//
// SMEM floats:
//   Ws : 32 x 1032                      = 33024
//   Hs : 64 x 132                       =  8448
//   Gs : 64 x 72 (two 32-col halves)    =  4608
//   cs : 512                            =   512
#define SM_WS 0
#define SM_HS (SM_WS + 32 * 1032)
#define SM_GS (SM_HS + 64 * 132)
#define SM_CS (SM_GS + 64 * 72)
#define SM_FLOATS (SM_CS + 512)

__global__ void __launch_bounds__(NTHR, 1)
lstm_seq_kernel(const float* __restrict__ Wh,   // [H4, HIDN] layer base
                const float* __restrict__ Xp,   // [TT, BSZ, H4]
                float* Htraj,                   // [TT, BSZ, HIDN]
                float* __restrict__ gC) {       // [BSZ, HIDN] final cell out
    extern __shared__ float sm[];
    float* Ws = sm + SM_WS;
    float* Hs = sm + SM_HS;
    float* Gs = sm + SM_GS;
    float* cs = sm + SM_CS;

    const int tid  = threadIdx.x;
    const int warp = tid >> 5;
    const int wk   = warp >> 3;        // 0..1 K-half
    const int wm   = (warp >> 1) & 3;  // 0..3 batch tile
    const int wn   = warp & 1;         // 0..1 col tile
    const int j0   = blockIdx.x * UPC;

    // ---- preload Wh slice: smem row n (0..31) = gate (n>>3), unit (n&7) ----
    for (int i4 = tid; i4 < 32 * 256; i4 += NTHR) {
        int n  = i4 >> 8;
        int c4 = (i4 & 255) * 4;
        int row = (n >> 3) * HIDN + j0 + (n & 7);
        *(float4*)&Ws[n * 1032 + c4] = *(const float4*)(Wh + (size_t)row * HIDN + c4);
    }
    if (tid < 512) cs[tid] = 0.f;
    __syncthreads();

    // staging thread mapping: 512 threads cover 64 rows x 32 float4 per pass,
    // 4 passes -> rows (tid>>5) + r*16, col4 = (tid&31)*4
    const int srow = tid >> 5;
    const int sc4  = (tid & 31) * 4;

    // epilogue mapping: one element per thread
    const int eb = tid >> 3;       // batch 0..63
    const int eu = tid & 7;        // unit 0..7

    for (int t = 0; t < TT; t++) {
        // prefetch Xp gate pre-activations for this thread's element (DRAM)
        const float* xb = Xp + (size_t)t * BSZ * H4 + (size_t)eb * H4 + j0 + eu;
        float x_i = xb[0];
        float x_f = xb[HIDN];
        float x_o = xb[2 * HIDN];
        float x_c = xb[3 * HIDN];

        wmma::fragment<wmma::accumulator, 16, 16, 8, float> acc[2];
        wmma::fill_fragment(acc[0], 0.f);
        wmma::fill_fragment(acc[1], 0.f);

        if (t > 0) {
            const float* Hprev = Htraj + (size_t)(t - 1) * BH;
            float4 pf[4];
#pragma unroll
            for (int r = 0; r < 4; r++)
                pf[r] = *(const float4*)(Hprev + (size_t)(srow + r * 16) * HIDN + sc4);

            for (int it = 0; it < 8; it++) {
#pragma unroll
                for (int r = 0; r < 4; r++)
                    *(float4*)&Hs[(srow + r * 16) * 132 + sc4] = pf[r];
                __syncthreads();
                if (it < 7) {
                    int k0n = (it + 1) * 128;
#pragma unroll
                    for (int r = 0; r < 4; r++)
                        pf[r] = *(const float4*)(Hprev + (size_t)(srow + r * 16) * HIDN + k0n + sc4);
                }
#pragma unroll
                for (int kk = 0; kk < 64; kk += 8) {
                    wmma::fragment<wmma::matrix_a, 16, 16, 8, wmma::precision::tf32, wmma::row_major> af;
                    wmma::load_matrix_sync(af, &Hs[(wm * 16) * 132 + wk * 64 + kk], 132);
#pragma unroll
                    for (int i = 0; i < af.num_elements; i++) af.x[i] = wmma::__float_to_tf32(af.x[i]);
                    wmma::fragment<wmma::matrix_b, 16, 16, 8, wmma::precision::tf32, wmma::col_major> bf;
                    wmma::load_matrix_sync(bf, &Ws[(wn * 16) * 1032 + it * 128 + wk * 64 + kk], 1032);
#pragma unroll
                    for (int i = 0; i < bf.num_elements; i++) bf.x[i] = wmma::__float_to_tf32(bf.x[i]);
                    wmma::mma_sync(acc[(kk >> 3) & 1], af, bf, acc[(kk >> 3) & 1]);
                }
                __syncthreads();
            }
        }

        // sum the two local accumulators, store K-half partial to Gs
#pragma unroll
        for (int i = 0; i < acc[0].num_elements; i++) acc[0].x[i] += acc[1].x[i];
        wmma::store_matrix_sync(&Gs[(wm * 16) * 72 + wk * 36 + wn * 16], acc[0], 72,
                                wmma::mem_row_major);
        __syncthreads();

        // ---- LSTM cell epilogue: one element per thread ----
        {
            float gi = Gs[eb * 72 + eu]           + Gs[eb * 72 + 36 + eu]           + x_i;
            float gf = Gs[eb * 72 + 8 + eu]       + Gs[eb * 72 + 36 + 8 + eu]       + x_f;
            float go = Gs[eb * 72 + 16 + eu]      + Gs[eb * 72 + 36 + 16 + eu]      + x_o;
            float gc = Gs[eb * 72 + 24 + eu]      + Gs[eb * 72 + 36 + 24 + eu]      + x_c;
            float si = 1.f / (1.f + expf(-gi));
            float sf = 1.f / (1.f + expf(-gf));
            float so = 1.f / (1.f + expf(-go));
            float cn = sf * cs[tid] + si * tanhf(gc);
            cs[tid] = cn;
            Htraj[(size_t)t * BH + (size_t)eb * HIDN + j0 + eu] = so * tanhf(cn);
        }

        // ---- grid barrier ----
        __threadfence();
        __syncthreads();
        if (tid == 0) {
            atomicAdd(&g_bar, 1u);
            unsigned target = (unsigned)(t + 1) * NCTA;
            while (*((volatile unsigned*)&g_bar) < target) { }
        }
        __syncthreads();
        __threadfence();
    }

    // ---- final cell state ----
    gC[(size_t)eb * HIDN + j0 + eu] = cs[tid];
}

// ---------------- finalize: Hf / Cf ----------------
__global__ void finalize_kernel(const float* __restrict__ h0_last,
                                const float* __restrict__ h1_last,
                                float* __restrict__ Hf,
                                float* __restrict__ Cf) {
    int i = blockIdx.x * blockDim.x + threadIdx.x;
    if (i < BH) {
        Hf[i]      = h0_last[i];
        Hf[BH + i] = h1_last[i];
        Cf[i]      = g_c[0][i];
        Cf[BH + i] = g_c[1][i];
    }
}

// ---------------- launch ----------------
extern "C" void kernel_launch(void* const* d_in, const int* in_sizes, int n_in,
                              void* d_out, int out_size) {
    const float* X    = (const float*)d_in[0]; // [T, B, D]
    const float* Wx   = (const float*)d_in[1]; // [L, 4H, D]
    const float* Wh   = (const float*)d_in[2]; // [L, 4H, H]
    const float* bias = (const float*)d_in[3]; // [L, 4H]

    float* out     = (float*)d_out;
    float* outputs = out;                              // [T, B, H]
    float* Hf      = out + (size_t)TT * BSZ * HIDN;
    float* Cf      = Hf + (size_t)NL * BH;

    float *Xp_p = nullptr, *H0_p = nullptr, *gc_p = nullptr;
    cudaGetSymbolAddress((void**)&Xp_p, g_Xp);
    cudaGetSymbolAddress((void**)&H0_p, g_H0);
    cudaGetSymbolAddress((void**)&gc_p, g_c);

    static bool attr_set = false;
    if (!attr_set) {
        cudaFuncSetAttribute(lstm_seq_kernel,
                             cudaFuncAttributeMaxDynamicSharedMemorySize,
                             SM_FLOATS * sizeof(float));
        attr_set = true;
    }

    dim3 gg(H4 / 64, MTOT / 64);

    // Layer 0
    gemm_xp_kernel<<<gg, 256>>>(X, Wx, bias, MTOT, H4, DIN);
    reset_bar_kernel<<<1, 32>>>();
    lstm_seq_kernel<<<NCTA, NTHR, SM_FLOATS * sizeof(float)>>>(
        Wh, Xp_p, H0_p, gc_p);

    // Layer 1
    gemm_xp_kernel<<<gg, 256>>>(H0_p, Wx + (size_t)H4 * DIN, bias + H4, MTOT, H4, HIDN);
    reset_bar_kernel<<<1, 32>>>();
    lstm_seq_kernel<<<NCTA, NTHR, SM_FLOATS * sizeof(float)>>>(
        Wh + (size_t)H4 * HIDN, Xp_p, outputs, gc_p + BH);

    finalize_kernel<<<(BH + 255) / 256, 256>>>(
        H0_p + (size_t)(TT - 1) * BH,
        outputs + (size_t)(TT - 1) * BH,
        Hf, Cf);
}